// round 7
// baseline (speedup 1.0000x reference)
#include <cuda_runtime.h>
#include <cstdint>

// ---------------- problem constants ----------------
#define NN 16
#define CC 64
#define HW 3136       // 56*56
#define WID 56

// ---------------- device scratch ----------------
__device__ float g_maxabs_x, g_maxw1, g_maxw2, g_max_r1, g_max_r2;
__device__ float g_part[512];
__device__ unsigned g_qxp[NN*16*HW];     // packed int8 qx: (n, c4, hw), byte j = channel 4*c4+j
__device__ unsigned g_q1p[NN*16*HW];     // packed uint8 q1
__device__ float    g_t1 [NN*CC*HW];     // bn1 output (pre-relu), fp32
__device__ unsigned g_qw1p[9216];        // packed weights: [c4][pos][o]
__device__ unsigned g_qw2p[9216];
__device__ int g_wsum1[4608], g_wsum2[4608];     // [cb][pos], cb = c*8+bit
__device__ int g_stats1[9*512], g_stats2[9*512]; // 9 stats x 512 channel-bits

__device__ __forceinline__ void atomicMaxF(float* a, float v) {
    atomicMax((int*)a, __float_as_int(v));   // valid for non-negative floats
}
__device__ __forceinline__ int dp4a_ss(unsigned a, unsigned b, int c) {
    int r; asm("dp4a.s32.s32 %0, %1, %2, %3;" : "=r"(r) : "r"(a), "r"(b), "r"(c)); return r;
}
__device__ __forceinline__ int dp4a_us(unsigned a, unsigned b, int c) {
    int r; asm("dp4a.u32.s32 %0, %1, %2, %3;" : "=r"(r) : "r"(a), "r"(b), "r"(c)); return r;
}
template<int PASS>
__device__ __forceinline__ int DP(unsigned a, unsigned b, int c) {
    return (PASS == 1) ? dp4a_ss(a, b, c) : dp4a_us(a, b, c);
}

// ---------------- reduceA: partial max|x| (0..511), max|w| (512,513), init (514)
__global__ void reduceA(const float4* __restrict__ x,
                        const float* __restrict__ w1, const float* __restrict__ w2) {
    int b = blockIdx.x;
    if (b == 514) {
        if (threadIdx.x == 0) { g_max_r1 = 0.f; g_max_r2 = 0.f; }
        for (int i = threadIdx.x; i < 4608; i += 256) { g_stats1[i] = 0; g_stats2[i] = 0; }
        return;
    }
    float m = 0.f;
    if (b < 512) {
        const int n4 = NN*CC*HW/4;
        for (int i = b*256 + threadIdx.x; i < n4; i += 512*256) {
            float4 v = x[i];
            m = fmaxf(m, fmaxf(fmaxf(fabsf(v.x), fabsf(v.y)), fmaxf(fabsf(v.z), fabsf(v.w))));
        }
    } else {
        const float* w = (b == 513) ? w2 : w1;
        for (int i = threadIdx.x; i < 36864; i += 256) m = fmaxf(m, fabsf(w[i]));
    }
    #pragma unroll
    for (int o = 16; o; o >>= 1) m = fmaxf(m, __shfl_xor_sync(0xffffffffu, m, o));
    __shared__ float sm[8];
    if ((threadIdx.x & 31) == 0) sm[threadIdx.x >> 5] = m;
    __syncthreads();
    if (threadIdx.x == 0) {
        float mm = sm[0];
        #pragma unroll
        for (int i = 1; i < 8; i++) mm = fmaxf(mm, sm[i]);
        if (b < 512) g_part[b] = mm;
        else if (b == 512) g_maxw1 = mm;
        else g_maxw2 = mm;
    }
}

// ---------------- fused quantize + bit stats (+ weight wsum blocks on PASS 1) --
// Data blocks 0..511: (n, c4, half); each handles 392 words (28 rows x 14).
// PASS 1 extra blocks 512..547: weight quant + pack + wsum (one warp per item).
template<int PASS>
__global__ void __launch_bounds__(256) quantStatsKernel(const float* __restrict__ xin,
                                                        const float* __restrict__ w1,
                                                        const float* __restrict__ w2) {
    const unsigned M = 0x01010101u;
    if (PASS == 1 && blockIdx.x >= 512) {
        // ---- weight quant + wsum: warp handles item (sel, c4, pos) ----
        int item = (blockIdx.x - 512)*8 + (threadIdx.x >> 5);
        int lane = threadIdx.x & 31;
        int sel = item / 144;
        int g   = item - sel*144;
        int c4  = g / 9, pos = g - c4*9;
        const float* w = sel ? w2 : w1;
        float s = (sel ? g_maxw2 : g_maxw1) * (1.0f/127.0f);
        unsigned* wpout = sel ? g_qw2p : g_qw1p;
        unsigned wds[2];
        #pragma unroll
        for (int h = 0; h < 2; h++) {
            int o = lane + 32*h;
            unsigned word = 0;
            #pragma unroll
            for (int j = 0; j < 4; j++) {
                float q = rintf(w[o*576 + (c4*4 + j)*9 + pos] / s);
                q = fminf(127.f, fmaxf(-127.f, q));
                word |= (((unsigned)(int)q) & 0xffu) << (8*j);
            }
            wpout[c4*576 + pos*64 + o] = word;
            wds[h] = word;
        }
        unsigned acc[8];
        #pragma unroll
        for (int k = 0; k < 8; k++) {
            unsigned v = ((wds[0] >> k) & M) + ((wds[1] >> k) & M);
            #pragma unroll
            for (int of = 16; of; of >>= 1) v += __shfl_xor_sync(0xffffffffu, v, of);
            acc[k] = v;
        }
        int j = lane >> 3, k = lane & 7;
        int* wsum = sel ? g_wsum2 : g_wsum1;
        wsum[((c4*4 + j)*8 + k)*9 + pos] = (int)((acc[k] >> (8*j)) & 0xffu);
        return;
    }

    int n    = blockIdx.x >> 5;         // 0..15
    int rem  = blockIdx.x & 31;
    int c4   = rem >> 1;                // 0..15
    int half = rem & 1;                 // 0..1
    const float* src = (PASS == 1) ? xin : (const float*)g_t1;
    const float4* s0 = (const float4*)(src + (size_t)(n*CC + c4*4)*HW);
    unsigned* qp = (PASS == 1) ? g_qxp : g_q1p;
    uint4* dst = (uint4*)(qp + (size_t)(n*16 + c4)*HW);

    __shared__ unsigned scCor[128];   // 4 corners x 32 (j*8+k)
    __shared__ unsigned ws[8*48];     // 8 warps x [aAll_lo(8), aAll_hi(8), R0(8), R55(8), C0(8), C55(8)]
    __shared__ float sMaxW[8];

    if (PASS == 1) {
        // inline final reduce of g_part (replaces a separate reduce launch)
        float mloc = 0.f;
        for (int i = threadIdx.x; i < 512; i += 256) mloc = fmaxf(mloc, g_part[i]);
        #pragma unroll
        for (int o = 16; o; o >>= 1) mloc = fmaxf(mloc, __shfl_xor_sync(0xffffffffu, mloc, o));
        if ((threadIdx.x & 31) == 0) sMaxW[threadIdx.x >> 5] = mloc;
    }
    if (threadIdx.x < 128) scCor[threadIdx.x] = 0;
    __syncthreads();

    float s;
    if (PASS == 1) {
        float mm = sMaxW[0];
        #pragma unroll
        for (int i = 1; i < 8; i++) mm = fmaxf(mm, sMaxW[i]);
        if (blockIdx.x == 0 && threadIdx.x == 0) g_maxabs_x = mm;
        s = mm * (1.0f/127.0f);
    } else {
        s = g_max_r1 * (1.0f/255.0f);
    }
    float sinv = 1.0f / s;

    unsigned aAll[8] = {0,0,0,0,0,0,0,0};
    unsigned aR0 [8] = {0,0,0,0,0,0,0,0};
    unsigned aR55[8] = {0,0,0,0,0,0,0,0};
    unsigned aC0 [8] = {0,0,0,0,0,0,0,0};
    unsigned aC55[8] = {0,0,0,0,0,0,0,0};

    int ibase = half * 392;
    for (int li = threadIdx.x; li < 392; li += 256) {
        int i = ibase + li;
        float4 f0 = s0[i];
        float4 f1 = s0[784 + i];
        float4 f2 = s0[1568 + i];
        float4 f3 = s0[2352 + i];
        float q0[4], q1v[4], q2[4], q3[4];
        #pragma unroll
        for (int j = 0; j < 4; j++) {
            float vx = (j==0)?f0.x:(j==1)?f1.x:(j==2)?f2.x:f3.x;
            float vy = (j==0)?f0.y:(j==1)?f1.y:(j==2)?f2.y:f3.y;
            float vz = (j==0)?f0.z:(j==1)?f1.z:(j==2)?f2.z:f3.z;
            float vw = (j==0)?f0.w:(j==1)?f1.w:(j==2)?f2.w:f3.w;
            if (PASS == 1) {
                q0[j]  = fminf(127.f, fmaxf(-127.f, rintf(vx * sinv)));
                q1v[j] = fminf(127.f, fmaxf(-127.f, rintf(vy * sinv)));
                q2[j]  = fminf(127.f, fmaxf(-127.f, rintf(vz * sinv)));
                q3[j]  = fminf(127.f, fmaxf(-127.f, rintf(vw * sinv)));
            } else {
                q0[j]  = fminf(255.f, rintf(fmaxf(vx, 0.f) * sinv));
                q1v[j] = fminf(255.f, rintf(fmaxf(vy, 0.f) * sinv));
                q2[j]  = fminf(255.f, rintf(fmaxf(vz, 0.f) * sinv));
                q3[j]  = fminf(255.f, rintf(fmaxf(vw, 0.f) * sinv));
            }
        }
        unsigned w[4] = {0,0,0,0};
        #pragma unroll
        for (int j = 0; j < 4; j++) {
            w[0] |= (((unsigned)(int)q0[j])  & 0xffu) << (8*j);
            w[1] |= (((unsigned)(int)q1v[j]) & 0xffu) << (8*j);
            w[2] |= (((unsigned)(int)q2[j])  & 0xffu) << (8*j);
            w[3] |= (((unsigned)(int)q3[j])  & 0xffu) << (8*j);
        }
        dst[i] = make_uint4(w[0], w[1], w[2], w[3]);

        bool h0  = (half == 0) && (li < 14);
        bool h55 = (half == 1) && (li >= 378);
        int  im  = li % 14;
        bool w0f  = (im == 0);
        bool w55f = (im == 13);

        #pragma unroll
        for (int e = 0; e < 4; e++) {
            unsigned u = w[e];
            #pragma unroll
            for (int k = 0; k < 8; k++) {
                unsigned bits = (u >> k) & M;
                aAll[k] += bits;
                if (h0)  aR0 [k] += bits;
                if (h55) aR55[k] += bits;
            }
        }
        if (w0f) {
            unsigned u = w[0];
            #pragma unroll
            for (int k = 0; k < 8; k++) aC0[k] += (u >> k) & M;
        }
        if (w55f) {
            unsigned u = w[3];
            #pragma unroll
            for (int k = 0; k < 8; k++) aC55[k] += (u >> k) & M;
        }
        // corners: global i 0 (0,0) w0; 13 (0,55) w3; 770 (55,0) w0; 783 (55,55) w3
        if ((h0 || h55) && (w0f || w55f)) {
            int corner = (h55 ? 2 : 0) + (w55f ? 1 : 0);
            unsigned u = w55f ? w[3] : w[0];
            #pragma unroll
            for (int l = 0; l < 32; l++)
                atomicAdd(&scCor[corner*32 + l], (u >> l) & 1u);
        }
    }

    // split aAll to 16-bit lanes (lo = bytes 0,2 -> channels j=0,2; hi = bytes 1,3)
    unsigned aLo[8], aHi[8];
    #pragma unroll
    for (int k = 0; k < 8; k++) {
        aLo[k] = aAll[k] & 0x00FF00FFu;
        aHi[k] = (aAll[k] >> 8) & 0x00FF00FFu;
    }
    #pragma unroll
    for (int k = 0; k < 8; k++) {
        #pragma unroll
        for (int o = 16; o; o >>= 1) {
            aLo [k] += __shfl_xor_sync(0xffffffffu, aLo [k], o);
            aHi [k] += __shfl_xor_sync(0xffffffffu, aHi [k], o);
            aR0 [k] += __shfl_xor_sync(0xffffffffu, aR0 [k], o);
            aR55[k] += __shfl_xor_sync(0xffffffffu, aR55[k], o);
            aC0 [k] += __shfl_xor_sync(0xffffffffu, aC0 [k], o);
            aC55[k] += __shfl_xor_sync(0xffffffffu, aC55[k], o);
        }
    }
    int warp = threadIdx.x >> 5;
    if ((threadIdx.x & 31) == 0) {
        #pragma unroll
        for (int k = 0; k < 8; k++) {
            ws[warp*48 +      k] = aLo [k];
            ws[warp*48 +  8 + k] = aHi [k];
            ws[warp*48 + 16 + k] = aR0 [k];
            ws[warp*48 + 24 + k] = aR55[k];
            ws[warp*48 + 32 + k] = aC0 [k];
            ws[warp*48 + 40 + k] = aC55[k];
        }
    }
    __syncthreads();

    int* stats = (PASS == 1) ? g_stats1 : g_stats2;
    if (threadIdx.x < 8) {
        int k = threadIdx.x;
        unsigned vlo = 0, vhi = 0;
        #pragma unroll
        for (int wp = 0; wp < 8; wp++) {
            vlo += ws[wp*48 +     k];
            vhi += ws[wp*48 + 8 + k];
        }
        atomicAdd(&stats[(c4*4 + 0)*8 + k], (int)(vlo & 0xffffu));
        atomicAdd(&stats[(c4*4 + 2)*8 + k], (int)(vlo >> 16));
        atomicAdd(&stats[(c4*4 + 1)*8 + k], (int)(vhi & 0xffffu));
        atomicAdd(&stats[(c4*4 + 3)*8 + k], (int)(vhi >> 16));
    } else if (threadIdx.x < 40) {
        int t2   = threadIdx.x - 8;
        int sidx = 1 + (t2 >> 3);          // regions 1..4 (R0, R55, C0, C55)
        int k    = t2 & 7;
        unsigned v = 0;
        #pragma unroll
        for (int wp = 0; wp < 8; wp++) v += ws[wp*48 + 8 + sidx*8 + k];
        #pragma unroll
        for (int j = 0; j < 4; j++)
            atomicAdd(&stats[sidx*512 + (c4*4 + j)*8 + k], (int)((v >> (8*j)) & 0xffu));
    }
    if (threadIdx.x < 128) {
        int corner = threadIdx.x >> 5;
        int l = threadIdx.x & 31;
        int j = l >> 3, k = l & 7;
        int v = (int)scCor[threadIdx.x];
        if (v) atomicAdd(&stats[(5 + corner)*512 + (c4*4 + j)*8 + k], v);
    }
}

// ---------------- int8 DP4A conv + fused BN (+identity) + max-relu ----------------
// 128 threads: ot = tid>>3 (16 out-channel groups), cg = tid&7 (7-col groups)
// each thread: 2 output rows x 7 cols x 4 out channels
template<int PASS>
__global__ void __launch_bounds__(128, 3) convKernel(
    const float* __restrict__ gamma, const float* __restrict__ beta,
    const float* __restrict__ mean,  const float* __restrict__ var,
    float* __restrict__ dOut)
{
    const unsigned* __restrict__ inP = (PASS == 1) ? g_qxp : g_q1p;
    const uint4* __restrict__ wP = (const uint4*)((PASS == 1) ? g_qw1p : g_qw2p);
    int n  = blockIdx.x / 28;
    int r0 = (blockIdx.x - n*28) * 2;

    __shared__ unsigned sIn[16*4*58];   // [c4][rows r0-1..r0+2][58 cols, -1 halo]
    for (int i = threadIdx.x; i < 16*4*58; i += 128) {
        int c4 = i / 232;
        int r2 = i - c4*232;
        int rr = r2 / 58;
        int cc = r2 - rr*58;
        int gr = r0 - 1 + rr, gc = cc - 1;
        unsigned v = 0;
        if ((unsigned)gr < 56u && (unsigned)gc < 56u)
            v = inP[(n*16 + c4)*HW + gr*WID + gc];
        sIn[i] = v;
    }
    __syncthreads();

    int ot    = threadIdx.x >> 3;       // 0..15
    int cbase = (threadIdx.x & 7) * 7;  // 0..49

    int acc[2][4][7];
    #pragma unroll
    for (int lr = 0; lr < 2; lr++)
        #pragma unroll
        for (int j = 0; j < 4; j++)
            #pragma unroll
            for (int p = 0; p < 7; p++) acc[lr][j][p] = 0;

    const unsigned* sp = sIn + cbase;
    #pragma unroll 1
    for (int c4 = 0; c4 < 16; c4++) {
        const uint4* wpc = wP + c4*144 + ot;
        uint4 wv[9];
        #pragma unroll
        for (int q = 0; q < 9; q++) wv[q] = __ldg(wpc + q*16);
        const unsigned* spc = sp + c4*232;
        #pragma unroll
        for (int ir = 0; ir < 4; ir++) {
            unsigned iv[9];
            #pragma unroll
            for (int dc = 0; dc < 9; dc++) iv[dc] = spc[ir*58 + dc];
            if (ir < 3) {               // output row 0, dr = ir
                #pragma unroll
                for (int tt = 0; tt < 3; tt++) {
                    uint4 w4 = wv[ir*3 + tt];
                    unsigned wc[4] = {w4.x, w4.y, w4.z, w4.w};
                    #pragma unroll
                    for (int px = 0; px < 7; px++) {
                        unsigned a = iv[px + tt];
                        #pragma unroll
                        for (int j = 0; j < 4; j++)
                            acc[0][j][px] = DP<PASS>(a, wc[j], acc[0][j][px]);
                    }
                }
            }
            if (ir >= 1) {              // output row 1, dr = ir-1
                #pragma unroll
                for (int tt = 0; tt < 3; tt++) {
                    uint4 w4 = wv[(ir-1)*3 + tt];
                    unsigned wc[4] = {w4.x, w4.y, w4.z, w4.w};
                    #pragma unroll
                    for (int px = 0; px < 7; px++) {
                        unsigned a = iv[px + tt];
                        #pragma unroll
                        for (int j = 0; j < 4; j++)
                            acc[1][j][px] = DP<PASS>(a, wc[j], acc[1][j][px]);
                    }
                }
            }
        }
    }

    float sp1, sx = 0.f;
    if (PASS == 1) {
        sp1 = (g_maxabs_x * (1.f/127.f)) * (g_maxw1 * (1.f/127.f));
    } else {
        sp1 = (g_max_r1 * (1.f/255.f)) * (g_maxw2 * (1.f/127.f));
        sx  = g_maxabs_x * (1.f/127.f);
    }
    float A[4], B[4];
    #pragma unroll
    for (int j = 0; j < 4; j++) {
        int o = ot*4 + j;
        float inv = gamma[o] / sqrtf(var[o] + 1e-5f);
        A[j] = sp1 * inv;
        B[j] = beta[o] - mean[o]*inv;
    }

    float* dstp = (PASS == 1) ? g_t1 : dOut;
    float mx = 0.f;
    #pragma unroll
    for (int lr = 0; lr < 2; lr++) {
        int hwb = (r0 + lr)*WID + cbase;
        #pragma unroll
        for (int px = 0; px < 7; px++) {
            int hw = hwb + px;
            unsigned idw = 0;
            if (PASS == 2) idw = g_qxp[(n*16 + ot)*HW + hw];
            #pragma unroll
            for (int j = 0; j < 4; j++) {
                float t = (float)acc[lr][j][px] * A[j] + B[j];
                if (PASS == 2) {
                    int qb = (int)((int8_t)((idw >> (8*j)) & 0xffu));
                    t += (float)qb * sx;
                }
                dstp[(n*CC + ot*4 + j)*HW + hw] = t;
                mx = fmaxf(mx, t);
            }
        }
    }
    #pragma unroll
    for (int o = 16; o; o >>= 1) mx = fmaxf(mx, __shfl_xor_sync(0xffffffffu, mx, o));
    __shared__ float smx[4];
    if ((threadIdx.x & 31) == 0) smx[threadIdx.x >> 5] = mx;
    __syncthreads();
    if (threadIdx.x == 0) {
        float m = fmaxf(fmaxf(smx[0], smx[1]), fmaxf(smx[2], smx[3]));
        atomicMaxF((PASS == 1) ? &g_max_r1 : &g_max_r2, m);
    }
}

// ---------------- HM_act / HM_energy from factorized stats ----------------
__device__ __forceinline__ long long energyFor(const int* stats, const int* wsum, int cb) {
    int S   = stats[        cb];
    int r0  = stats[ 512  + cb];
    int r55 = stats[1024  + cb];
    int c0  = stats[1536  + cb];
    int c55 = stats[2048  + cb];
    int s00 = stats[2560  + cb];
    int s0b = stats[3072  + cb];
    int sb0 = stats[3584  + cb];
    int sbb = stats[4096  + cb];
    long long en = 0;
    #pragma unroll
    for (int kh = 0; kh < 3; kh++) {
        #pragma unroll
        for (int kw = 0; kw < 3; kw++) {
            int xs = S;
            if (kh == 2) xs -= r0;  else if (kh == 0) xs -= r55;
            if (kw == 2) xs -= c0;  else if (kw == 0) xs -= c55;
            if (kh == 2 && kw == 2) xs += s00;
            if (kh == 2 && kw == 0) xs += s0b;
            if (kh == 0 && kw == 2) xs += sb0;
            if (kh == 0 && kw == 0) xs += sbb;
            en += (long long)wsum[cb*9 + kh*3 + kw] * (long long)xs;
        }
    }
    return en;
}

// ---------------- final QuantReLU on d_out (in place) + finalize (block 784) --
__global__ void __launch_bounds__(256) finalQuantFin(float* __restrict__ out) {
    if (blockIdx.x == 784) {
        int t = threadIdx.x;
        long long act = 0, en = 0;
        for (int cb = t; cb < 512; cb += 256) {
            act += (long long)g_stats1[cb] + (long long)g_stats2[cb];
            en  += energyFor(g_stats1, g_wsum1, cb) + energyFor(g_stats2, g_wsum2, cb);
        }
        __shared__ long long sa[256], se[256];
        sa[t] = act; se[t] = en;
        __syncthreads();
        for (int step = 128; step; step >>= 1) {
            if (t < step) { sa[t] += sa[t + step]; se[t] += se[t + step]; }
            __syncthreads();
        }
        if (t == 0) {
            out[NN*CC*HW    ] = (float)sa[0];   // HM_act
            out[NN*CC*HW + 1] = (float)se[0];   // HM_energy
        }
        return;
    }
    float s = g_max_r2 * (1.f/255.f);
    float sinv = 1.0f / s;
    float4* o4 = (float4*)out;
    int base = blockIdx.x*256 + threadIdx.x;
    #pragma unroll
    for (int it = 0; it < 4; it++) {
        int i = base + it*200704;
        float4 v = o4[i];
        v.x = fminf(255.f, rintf(fmaxf(v.x, 0.f) * sinv)) * s;
        v.y = fminf(255.f, rintf(fmaxf(v.y, 0.f) * sinv)) * s;
        v.z = fminf(255.f, rintf(fmaxf(v.z, 0.f) * sinv)) * s;
        v.w = fminf(255.f, rintf(fmaxf(v.w, 0.f) * sinv)) * s;
        o4[i] = v;
    }
}

// ---------------- launch ----------------
extern "C" void kernel_launch(void* const* d_in, const int* in_sizes, int n_in,
                              void* d_out, int out_size) {
    const float* x  = (const float*)d_in[0];
    const float* w1 = (const float*)d_in[1];
    const float* w2 = (const float*)d_in[2];
    const float* g1 = (const float*)d_in[3];
    const float* b1 = (const float*)d_in[4];
    const float* m1 = (const float*)d_in[5];
    const float* v1 = (const float*)d_in[6];
    const float* g2 = (const float*)d_in[7];
    const float* b2 = (const float*)d_in[8];
    const float* m2 = (const float*)d_in[9];
    const float* v2 = (const float*)d_in[10];
    float* out = (float*)d_out;

    reduceA<<<515, 256>>>((const float4*)x, w1, w2);
    quantStatsKernel<1><<<548, 256>>>(x, w1, w2);
    convKernel<1><<<448, 128>>>(g1, b1, m1, v1, nullptr);
    quantStatsKernel<2><<<512, 256>>>(nullptr, nullptr, nullptr);
    convKernel<2><<<448, 128>>>(g2, b2, m2, v2, out);
    finalQuantFin<<<785, 256>>>(out);
}

// round 8
// speedup vs baseline: 1.0569x; 1.0569x over previous
#include <cuda_runtime.h>
#include <cstdint>

// ---------------- problem constants ----------------
#define NN 16
#define CC 64
#define HW 3136       // 56*56
#define WID 56

// ---------------- device scratch ----------------
__device__ float g_maxabs_x, g_maxw1, g_maxw2, g_max_r1, g_max_r2;
__device__ float g_part[512];
__device__ unsigned g_qxp[NN*16*HW];     // packed int8 qx: (n, c4, hw), byte j = channel 4*c4+j
__device__ unsigned g_q1p[NN*16*HW];     // packed uint8 q1
__device__ float    g_t1 [NN*CC*HW];     // bn1 output (pre-relu), fp32
__device__ unsigned g_qw1p[9216];        // packed weights: [c4][pos][o]
__device__ unsigned g_qw2p[9216];
__device__ int g_wsum1[4608], g_wsum2[4608];     // [cb][pos], cb = c*8+bit
__device__ int g_stats1[9*512], g_stats2[9*512]; // 9 stats x 512 channel-bits

__device__ __forceinline__ void atomicMaxF(float* a, float v) {
    atomicMax((int*)a, __float_as_int(v));   // valid for non-negative floats
}
__device__ __forceinline__ int dp4a_ss(unsigned a, unsigned b, int c) {
    int r; asm("dp4a.s32.s32 %0, %1, %2, %3;" : "=r"(r) : "r"(a), "r"(b), "r"(c)); return r;
}
__device__ __forceinline__ int dp4a_us(unsigned a, unsigned b, int c) {
    int r; asm("dp4a.u32.s32 %0, %1, %2, %3;" : "=r"(r) : "r"(a), "r"(b), "r"(c)); return r;
}
template<int PASS>
__device__ __forceinline__ int DP(unsigned a, unsigned b, int c) {
    return (PASS == 1) ? dp4a_ss(a, b, c) : dp4a_us(a, b, c);
}

// ---------------- reduceA: partial max|x| (0..511), max|w| (512,513), init (514)
__global__ void reduceA(const float4* __restrict__ x,
                        const float* __restrict__ w1, const float* __restrict__ w2) {
    int b = blockIdx.x;
    if (b == 514) {
        if (threadIdx.x == 0) { g_max_r1 = 0.f; g_max_r2 = 0.f; }
        for (int i = threadIdx.x; i < 4608; i += 256) { g_stats1[i] = 0; g_stats2[i] = 0; }
        return;
    }
    float m = 0.f;
    if (b < 512) {
        const int n4 = NN*CC*HW/4;
        for (int i = b*256 + threadIdx.x; i < n4; i += 512*256) {
            float4 v = x[i];
            m = fmaxf(m, fmaxf(fmaxf(fabsf(v.x), fabsf(v.y)), fmaxf(fabsf(v.z), fabsf(v.w))));
        }
    } else {
        const float* w = (b == 513) ? w2 : w1;
        for (int i = threadIdx.x; i < 36864; i += 256) m = fmaxf(m, fabsf(w[i]));
    }
    #pragma unroll
    for (int o = 16; o; o >>= 1) m = fmaxf(m, __shfl_xor_sync(0xffffffffu, m, o));
    __shared__ float sm[8];
    if ((threadIdx.x & 31) == 0) sm[threadIdx.x >> 5] = m;
    __syncthreads();
    if (threadIdx.x == 0) {
        float mm = sm[0];
        #pragma unroll
        for (int i = 1; i < 8; i++) mm = fmaxf(mm, sm[i]);
        if (b < 512) g_part[b] = mm;
        else if (b == 512) g_maxw1 = mm;
        else g_maxw2 = mm;
    }
}

// ---------------- fused quantize + bit stats (+ weight wsum blocks on PASS 1) --
// Data blocks 0..511: (n, c4, half); each handles 392 words (28 rows x 14).
// Main loop counts ONLY aAll; borders recomputed by dedicated warps (0..2).
// PASS 1 extra blocks 512..547: weight quant + pack + wsum (one warp per item).
template<int PASS>
__global__ void __launch_bounds__(256) quantStatsKernel(const float* __restrict__ xin,
                                                        const float* __restrict__ w1,
                                                        const float* __restrict__ w2) {
    cudaGridDependencySynchronize();
    const unsigned M = 0x01010101u;
    if (PASS == 1 && blockIdx.x >= 512) {
        // ---- weight quant + wsum: warp handles item (sel, c4, pos) ----
        int item = (blockIdx.x - 512)*8 + (threadIdx.x >> 5);
        int lane = threadIdx.x & 31;
        int sel = item / 144;
        int g   = item - sel*144;
        int c4  = g / 9, pos = g - c4*9;
        const float* w = sel ? w2 : w1;
        float s = (sel ? g_maxw2 : g_maxw1) * (1.0f/127.0f);
        unsigned* wpout = sel ? g_qw2p : g_qw1p;
        unsigned wds[2];
        #pragma unroll
        for (int h = 0; h < 2; h++) {
            int o = lane + 32*h;
            unsigned word = 0;
            #pragma unroll
            for (int j = 0; j < 4; j++) {
                float q = rintf(w[o*576 + (c4*4 + j)*9 + pos] / s);
                q = fminf(127.f, fmaxf(-127.f, q));
                word |= (((unsigned)(int)q) & 0xffu) << (8*j);
            }
            wpout[c4*576 + pos*64 + o] = word;
            wds[h] = word;
        }
        unsigned acc[8];
        #pragma unroll
        for (int k = 0; k < 8; k++) {
            unsigned v = ((wds[0] >> k) & M) + ((wds[1] >> k) & M);
            #pragma unroll
            for (int of = 16; of; of >>= 1) v += __shfl_xor_sync(0xffffffffu, v, of);
            acc[k] = v;
        }
        int j = lane >> 3, k = lane & 7;
        int* wsum = sel ? g_wsum2 : g_wsum1;
        wsum[((c4*4 + j)*8 + k)*9 + pos] = (int)((acc[k] >> (8*j)) & 0xffu);
        return;
    }

    int n    = blockIdx.x >> 5;         // 0..15
    int rem  = blockIdx.x & 31;
    int c4   = rem >> 1;                // 0..15
    int half = rem & 1;                 // 0..1
    const float* src = (PASS == 1) ? xin : (const float*)g_t1;
    const float4* s0 = (const float4*)(src + (size_t)(n*CC + c4*4)*HW);
    unsigned* qp = (PASS == 1) ? g_qxp : g_q1p;
    uint4* dst = (uint4*)(qp + (size_t)(n*16 + c4)*HW);

    __shared__ unsigned scCor[128];   // 4 corners x 32 (j*8+k)
    __shared__ unsigned ws[8*48];     // 8 warps x [aAll_lo(8), aAll_hi(8), R0(8), R55(8), C0(8), C55(8)]
    __shared__ float sMaxW[8];

    if (PASS == 1) {
        float mloc = 0.f;
        for (int i = threadIdx.x; i < 512; i += 256) mloc = fmaxf(mloc, g_part[i]);
        #pragma unroll
        for (int o = 16; o; o >>= 1) mloc = fmaxf(mloc, __shfl_xor_sync(0xffffffffu, mloc, o));
        if ((threadIdx.x & 31) == 0) sMaxW[threadIdx.x >> 5] = mloc;
    }
    if (threadIdx.x < 128) scCor[threadIdx.x] = 0;
    __syncthreads();

    float s;
    if (PASS == 1) {
        float mm = sMaxW[0];
        #pragma unroll
        for (int i = 1; i < 8; i++) mm = fmaxf(mm, sMaxW[i]);
        if (blockIdx.x == 0 && threadIdx.x == 0) g_maxabs_x = mm;
        s = mm * (1.0f/127.0f);
    } else {
        s = g_max_r1 * (1.0f/255.0f);
    }
    float sinv = 1.0f / s;

    // quantize the word-quad at index i (hw = 4i..4i+3, 4 channels packed per word)
    auto quantQuad = [&](int i, unsigned w[4]) {
        float4 f0 = s0[i];
        float4 f1 = s0[784 + i];
        float4 f2 = s0[1568 + i];
        float4 f3 = s0[2352 + i];
        float q0[4], q1v[4], q2[4], q3[4];
        #pragma unroll
        for (int j = 0; j < 4; j++) {
            float vx = (j==0)?f0.x:(j==1)?f1.x:(j==2)?f2.x:f3.x;
            float vy = (j==0)?f0.y:(j==1)?f1.y:(j==2)?f2.y:f3.y;
            float vz = (j==0)?f0.z:(j==1)?f1.z:(j==2)?f2.z:f3.z;
            float vw = (j==0)?f0.w:(j==1)?f1.w:(j==2)?f2.w:f3.w;
            if (PASS == 1) {
                q0[j]  = fminf(127.f, fmaxf(-127.f, rintf(vx * sinv)));
                q1v[j] = fminf(127.f, fmaxf(-127.f, rintf(vy * sinv)));
                q2[j]  = fminf(127.f, fmaxf(-127.f, rintf(vz * sinv)));
                q3[j]  = fminf(127.f, fmaxf(-127.f, rintf(vw * sinv)));
            } else {
                q0[j]  = fminf(255.f, rintf(fmaxf(vx, 0.f) * sinv));
                q1v[j] = fminf(255.f, rintf(fmaxf(vy, 0.f) * sinv));
                q2[j]  = fminf(255.f, rintf(fmaxf(vz, 0.f) * sinv));
                q3[j]  = fminf(255.f, rintf(fmaxf(vw, 0.f) * sinv));
            }
        }
        w[0] = w[1] = w[2] = w[3] = 0;
        #pragma unroll
        for (int j = 0; j < 4; j++) {
            w[0] |= (((unsigned)(int)q0[j])  & 0xffu) << (8*j);
            w[1] |= (((unsigned)(int)q1v[j]) & 0xffu) << (8*j);
            w[2] |= (((unsigned)(int)q2[j])  & 0xffu) << (8*j);
            w[3] |= (((unsigned)(int)q3[j])  & 0xffu) << (8*j);
        }
    };

    // -------- main loop: quantize + store + aAll only --------
    unsigned aAll[8] = {0,0,0,0,0,0,0,0};
    int ibase = half * 392;
    for (int li = threadIdx.x; li < 392; li += 256) {
        int i = ibase + li;
        unsigned w[4];
        quantQuad(i, w);
        dst[i] = make_uint4(w[0], w[1], w[2], w[3]);
        #pragma unroll
        for (int k = 0; k < 8; k++)
            aAll[k] += ((w[0]>>k)&M) + ((w[1]>>k)&M) + ((w[2]>>k)&M) + ((w[3]>>k)&M);
    }

    // -------- borders: warp 0 = row border, warp 1 = col 0, warp 2 = col 55 ---
    unsigned aB[8] = {0,0,0,0,0,0,0,0};
    int warp = threadIdx.x >> 5;
    int lane = threadIdx.x & 31;
    if (warp == 0 && lane < 14) {
        int i = half ? 770 + lane : lane;
        unsigned w[4];
        quantQuad(i, w);
        #pragma unroll
        for (int k = 0; k < 8; k++)
            aB[k] += ((w[0]>>k)&M) + ((w[1]>>k)&M) + ((w[2]>>k)&M) + ((w[3]>>k)&M);
        if (lane == 0) {
            int corner = half ? 2 : 0;  unsigned u = w[0];
            #pragma unroll
            for (int l = 0; l < 32; l++) atomicAdd(&scCor[corner*32 + l], (u >> l) & 1u);
        }
        if (lane == 13) {
            int corner = half ? 3 : 1;  unsigned u = w[3];
            #pragma unroll
            for (int l = 0; l < 32; l++) atomicAdd(&scCor[corner*32 + l], (u >> l) & 1u);
        }
    } else if (warp == 1 && lane < 28) {
        int i = ibase + lane*14;        // column 0 word (hw%56 == 0..3 -> w[0])
        unsigned w[4];
        quantQuad(i, w);
        #pragma unroll
        for (int k = 0; k < 8; k++) aB[k] += (w[0] >> k) & M;
    } else if (warp == 2 && lane < 28) {
        int i = ibase + lane*14 + 13;   // column 55 word -> w[3]
        unsigned w[4];
        quantQuad(i, w);
        #pragma unroll
        for (int k = 0; k < 8; k++) aB[k] += (w[3] >> k) & M;
    }

    // split aAll to 16-bit lanes (warp-sum of byte lanes can reach 256)
    unsigned aLo[8], aHi[8];
    #pragma unroll
    for (int k = 0; k < 8; k++) {
        aLo[k] = aAll[k] & 0x00FF00FFu;
        aHi[k] = (aAll[k] >> 8) & 0x00FF00FFu;
    }
    #pragma unroll
    for (int k = 0; k < 8; k++) {
        #pragma unroll
        for (int o = 16; o; o >>= 1) {
            aLo[k] += __shfl_xor_sync(0xffffffffu, aLo[k], o);
            aHi[k] += __shfl_xor_sync(0xffffffffu, aHi[k], o);
            aB [k] += __shfl_xor_sync(0xffffffffu, aB [k], o);
        }
    }
    if (lane == 0) {
        #pragma unroll
        for (int k = 0; k < 8; k++) {
            ws[warp*48 +     k] = aLo[k];
            ws[warp*48 + 8 + k] = aHi[k];
        }
        #pragma unroll
        for (int slot = 0; slot < 4; slot++)
            #pragma unroll
            for (int k = 0; k < 8; k++) ws[warp*48 + 16 + slot*8 + k] = 0;
        int region = (warp == 0) ? (half ? 2 : 1) : (warp == 1) ? 3 : (warp == 2) ? 4 : 0;
        if (region) {
            #pragma unroll
            for (int k = 0; k < 8; k++) ws[warp*48 + 16 + (region-1)*8 + k] = aB[k];
        }
    }
    __syncthreads();

    int* stats = (PASS == 1) ? g_stats1 : g_stats2;
    if (threadIdx.x < 8) {
        int k = threadIdx.x;
        unsigned vlo = 0, vhi = 0;
        #pragma unroll
        for (int wp = 0; wp < 8; wp++) {
            vlo += ws[wp*48 +     k];
            vhi += ws[wp*48 + 8 + k];
        }
        atomicAdd(&stats[(c4*4 + 0)*8 + k], (int)(vlo & 0xffffu));
        atomicAdd(&stats[(c4*4 + 2)*8 + k], (int)(vlo >> 16));
        atomicAdd(&stats[(c4*4 + 1)*8 + k], (int)(vhi & 0xffffu));
        atomicAdd(&stats[(c4*4 + 3)*8 + k], (int)(vhi >> 16));
    } else if (threadIdx.x < 40) {
        int t2   = threadIdx.x - 8;
        int sidx = 1 + (t2 >> 3);          // regions 1..4 (R0, R55, C0, C55)
        int k    = t2 & 7;
        unsigned v = 0;
        #pragma unroll
        for (int wp = 0; wp < 8; wp++) v += ws[wp*48 + 8 + sidx*8 + k];
        #pragma unroll
        for (int j = 0; j < 4; j++)
            atomicAdd(&stats[sidx*512 + (c4*4 + j)*8 + k], (int)((v >> (8*j)) & 0xffu));
    }
    if (threadIdx.x < 128) {
        int corner = threadIdx.x >> 5;
        int l = threadIdx.x & 31;
        int j = l >> 3, k = l & 7;
        int v = (int)scCor[threadIdx.x];
        if (v) atomicAdd(&stats[(5 + corner)*512 + (c4*4 + j)*8 + k], v);
    }
}

// ---------------- int8 DP4A conv + fused BN (+identity) + max-relu ----------------
template<int PASS>
__global__ void __launch_bounds__(128, 3) convKernel(
    const float* __restrict__ gamma, const float* __restrict__ beta,
    const float* __restrict__ mean,  const float* __restrict__ var,
    float* __restrict__ dOut)
{
    cudaGridDependencySynchronize();
    const unsigned* __restrict__ inP = (PASS == 1) ? g_qxp : g_q1p;
    const uint4* __restrict__ wP = (const uint4*)((PASS == 1) ? g_qw1p : g_qw2p);
    int n  = blockIdx.x / 28;
    int r0 = (blockIdx.x - n*28) * 2;

    __shared__ unsigned sIn[16*4*58];   // [c4][rows r0-1..r0+2][58 cols, -1 halo]
    for (int i = threadIdx.x; i < 16*4*58; i += 128) {
        int c4 = i / 232;
        int r2 = i - c4*232;
        int rr = r2 / 58;
        int cc = r2 - rr*58;
        int gr = r0 - 1 + rr, gc = cc - 1;
        unsigned v = 0;
        if ((unsigned)gr < 56u && (unsigned)gc < 56u)
            v = inP[(n*16 + c4)*HW + gr*WID + gc];
        sIn[i] = v;
    }
    __syncthreads();

    int ot    = threadIdx.x >> 3;       // 0..15
    int cbase = (threadIdx.x & 7) * 7;  // 0..49

    int acc[2][4][7];
    #pragma unroll
    for (int lr = 0; lr < 2; lr++)
        #pragma unroll
        for (int j = 0; j < 4; j++)
            #pragma unroll
            for (int p = 0; p < 7; p++) acc[lr][j][p] = 0;

    const unsigned* sp = sIn + cbase;
    #pragma unroll 1
    for (int c4 = 0; c4 < 16; c4++) {
        const uint4* wpc = wP + c4*144 + ot;
        uint4 wv[9];
        #pragma unroll
        for (int q = 0; q < 9; q++) wv[q] = __ldg(wpc + q*16);
        const unsigned* spc = sp + c4*232;
        #pragma unroll
        for (int ir = 0; ir < 4; ir++) {
            unsigned iv[9];
            #pragma unroll
            for (int dc = 0; dc < 9; dc++) iv[dc] = spc[ir*58 + dc];
            if (ir < 3) {
                #pragma unroll
                for (int tt = 0; tt < 3; tt++) {
                    uint4 w4 = wv[ir*3 + tt];
                    unsigned wc[4] = {w4.x, w4.y, w4.z, w4.w};
                    #pragma unroll
                    for (int px = 0; px < 7; px++) {
                        unsigned a = iv[px + tt];
                        #pragma unroll
                        for (int j = 0; j < 4; j++)
                            acc[0][j][px] = DP<PASS>(a, wc[j], acc[0][j][px]);
                    }
                }
            }
            if (ir >= 1) {
                #pragma unroll
                for (int tt = 0; tt < 3; tt++) {
                    uint4 w4 = wv[(ir-1)*3 + tt];
                    unsigned wc[4] = {w4.x, w4.y, w4.z, w4.w};
                    #pragma unroll
                    for (int px = 0; px < 7; px++) {
                        unsigned a = iv[px + tt];
                        #pragma unroll
                        for (int j = 0; j < 4; j++)
                            acc[1][j][px] = DP<PASS>(a, wc[j], acc[1][j][px]);
                    }
                }
            }
        }
    }

    float sp1, sx = 0.f;
    if (PASS == 1) {
        sp1 = (g_maxabs_x * (1.f/127.f)) * (g_maxw1 * (1.f/127.f));
    } else {
        sp1 = (g_max_r1 * (1.f/255.f)) * (g_maxw2 * (1.f/127.f));
        sx  = g_maxabs_x * (1.f/127.f);
    }
    float A[4], B[4];
    #pragma unroll
    for (int j = 0; j < 4; j++) {
        int o = ot*4 + j;
        float inv = gamma[o] / sqrtf(var[o] + 1e-5f);
        A[j] = sp1 * inv;
        B[j] = beta[o] - mean[o]*inv;
    }

    float* dstp = (PASS == 1) ? g_t1 : dOut;
    float mx = 0.f;
    #pragma unroll
    for (int lr = 0; lr < 2; lr++) {
        int hwb = (r0 + lr)*WID + cbase;
        #pragma unroll
        for (int px = 0; px < 7; px++) {
            int hw = hwb + px;
            unsigned idw = 0;
            if (PASS == 2) idw = g_qxp[(n*16 + ot)*HW + hw];
            #pragma unroll
            for (int j = 0; j < 4; j++) {
                float t = (float)acc[lr][j][px] * A[j] + B[j];
                if (PASS == 2) {
                    int qb = (int)((int8_t)((idw >> (8*j)) & 0xffu));
                    t += (float)qb * sx;
                }
                dstp[(n*CC + ot*4 + j)*HW + hw] = t;
                mx = fmaxf(mx, t);
            }
        }
    }
    #pragma unroll
    for (int o = 16; o; o >>= 1) mx = fmaxf(mx, __shfl_xor_sync(0xffffffffu, mx, o));
    __shared__ float smx[4];
    if ((threadIdx.x & 31) == 0) smx[threadIdx.x >> 5] = mx;
    __syncthreads();
    if (threadIdx.x == 0) {
        float m = fmaxf(fmaxf(smx[0], smx[1]), fmaxf(smx[2], smx[3]));
        atomicMaxF((PASS == 1) ? &g_max_r1 : &g_max_r2, m);
    }
}

// ---------------- HM_act / HM_energy from factorized stats ----------------
__device__ __forceinline__ long long energyFor(const int* stats, const int* wsum, int cb) {
    int S   = stats[        cb];
    int r0  = stats[ 512  + cb];
    int r55 = stats[1024  + cb];
    int c0  = stats[1536  + cb];
    int c55 = stats[2048  + cb];
    int s00 = stats[2560  + cb];
    int s0b = stats[3072  + cb];
    int sb0 = stats[3584  + cb];
    int sbb = stats[4096  + cb];
    long long en = 0;
    #pragma unroll
    for (int kh = 0; kh < 3; kh++) {
        #pragma unroll
        for (int kw = 0; kw < 3; kw++) {
            int xs = S;
            if (kh == 2) xs -= r0;  else if (kh == 0) xs -= r55;
            if (kw == 2) xs -= c0;  else if (kw == 0) xs -= c55;
            if (kh == 2 && kw == 2) xs += s00;
            if (kh == 2 && kw == 0) xs += s0b;
            if (kh == 0 && kw == 2) xs += sb0;
            if (kh == 0 && kw == 0) xs += sbb;
            en += (long long)wsum[cb*9 + kh*3 + kw] * (long long)xs;
        }
    }
    return en;
}

// ---------------- final QuantReLU on d_out (in place) + finalize (block 784) --
__global__ void __launch_bounds__(256) finalQuantFin(float* __restrict__ out) {
    cudaGridDependencySynchronize();
    if (blockIdx.x == 784) {
        int t = threadIdx.x;
        long long act = 0, en = 0;
        for (int cb = t; cb < 512; cb += 256) {
            act += (long long)g_stats1[cb] + (long long)g_stats2[cb];
            en  += energyFor(g_stats1, g_wsum1, cb) + energyFor(g_stats2, g_wsum2, cb);
        }
        __shared__ long long sa[256], se[256];
        sa[t] = act; se[t] = en;
        __syncthreads();
        for (int step = 128; step; step >>= 1) {
            if (t < step) { sa[t] += sa[t + step]; se[t] += se[t + step]; }
            __syncthreads();
        }
        if (t == 0) {
            out[NN*CC*HW    ] = (float)sa[0];   // HM_act
            out[NN*CC*HW + 1] = (float)se[0];   // HM_energy
        }
        return;
    }
    float s = g_max_r2 * (1.f/255.f);
    float sinv = 1.0f / s;
    float4* o4 = (float4*)out;
    int base = blockIdx.x*256 + threadIdx.x;
    #pragma unroll
    for (int it = 0; it < 4; it++) {
        int i = base + it*200704;
        float4 v = o4[i];
        v.x = fminf(255.f, rintf(fmaxf(v.x, 0.f) * sinv)) * s;
        v.y = fminf(255.f, rintf(fmaxf(v.y, 0.f) * sinv)) * s;
        v.z = fminf(255.f, rintf(fmaxf(v.z, 0.f) * sinv)) * s;
        v.w = fminf(255.f, rintf(fmaxf(v.w, 0.f) * sinv)) * s;
        o4[i] = v;
    }
}

// ---------------- PDL launch helper ----------------
template <typename F, typename... Args>
static inline void launchPDL(F f, unsigned grid, unsigned block, Args... args) {
    cudaLaunchConfig_t cfg = {};
    cfg.gridDim  = dim3(grid, 1, 1);
    cfg.blockDim = dim3(block, 1, 1);
    cudaLaunchAttribute at[1];
    at[0].id = cudaLaunchAttributeProgrammaticStreamSerialization;
    at[0].val.programmaticStreamSerializationAllowed = 1;
    cfg.attrs = at;
    cfg.numAttrs = 1;
    cfg.stream = 0;
    cudaLaunchKernelEx(&cfg, f, args...);
}

// ---------------- launch ----------------
extern "C" void kernel_launch(void* const* d_in, const int* in_sizes, int n_in,
                              void* d_out, int out_size) {
    const float* x  = (const float*)d_in[0];
    const float* w1 = (const float*)d_in[1];
    const float* w2 = (const float*)d_in[2];
    const float* g1 = (const float*)d_in[3];
    const float* b1 = (const float*)d_in[4];
    const float* m1 = (const float*)d_in[5];
    const float* v1 = (const float*)d_in[6];
    const float* g2 = (const float*)d_in[7];
    const float* b2 = (const float*)d_in[8];
    const float* m2 = (const float*)d_in[9];
    const float* v2 = (const float*)d_in[10];
    float* out = (float*)d_out;

    reduceA<<<515, 256>>>((const float4*)x, w1, w2);
    launchPDL(quantStatsKernel<1>, 548, 256, x, w1, w2);
    launchPDL(convKernel<1>, 448, 128, g1, b1, m1, v1, (float*)nullptr);
    launchPDL(quantStatsKernel<2>, 512, 256, (const float*)nullptr, (const float*)nullptr, (const float*)nullptr);
    launchPDL(convKernel<2>, 448, 128, g2, b2, m2, v2, out);
    launchPDL(finalQuantFin, 785, 256, out);
}